// round 16
// baseline (speedup 1.0000x reference)
#include <cuda_runtime.h>
#include <cuda_fp16.h>
#include <mma.h>
#include <stdint.h>

using namespace nvcuda;

// Problem constants
#define NN 262144
#define EE (NN * 16)
#define CC 64
#define NVOXD 20
#define NVOX 8000
#define BN_EPS 1e-5f
#define GRID_INV 2.0f   // 1/0.5
#define FULLMASK 0xFFFFFFFFu
#define MAXDEG 64

typedef unsigned long long ull;
typedef long long ll;

// -------- scratch (all load-time zero; out_kernel re-zeroes accumulators each replay) ----
__device__ __half g_hh[NN * CC];          // h = x@W+b in fp16
__device__ float g_colsum[CC];
__device__ float g_colsq[CC];
__device__ float g_scale[CC];
__device__ float g_shift[CC];
__device__ int   g_negflag;               // any(scale<0)?
__device__ float g_xsum[NVOX * CC];
__device__ float g_psum[NVOX * 3];
__device__ float g_cnt[NVOX];
__device__ int   g_cnt_i[NN];             // in-degree
__device__ int   g_adj[NN * MAXDEG + 4];  // fixed-capacity buckets

// ======================= FAT kernel: wmma GEMM+stats blocks + scatter blocks =======================
// 18432 blocks: blockIdx%9==0 -> GEMM block (2048), else scatter block (16384).
// Interleaving co-schedules both workloads on every SM: GEMM is tensor/smem/DRAM-read
// bound, scatter is L2-atomic bound -> near-disjoint resources.
#define XS 80
#define WS 80
#define CSO 72
#define SM_X_BYTES (128 * XS * 2)
#define SM_W_OFF   SM_X_BYTES
#define SM_C_BYTES (128 * CSO * 4)
#define SM_RED_OFF SM_C_BYTES
#define GS_SMEM_BYTES (SM_C_BYTES + 512)
#define GEMM_BLOCKS (NN / 128)            // 2048
#define SCAT_BLOCKS (EE / 256)            // 16384
#define FAT_BLOCKS (GEMM_BLOCKS + SCAT_BLOCKS)   // 18432 = 2048*9

__device__ __forceinline__ void gemm_body(int gb, const float* __restrict__ x,
                                          const float* __restrict__ W,
                                          const float* __restrict__ b,
                                          char* smc) {
    __half* xs  = reinterpret_cast<__half*>(smc);
    __half* Wsf = reinterpret_cast<__half*>(smc + SM_W_OFF);
    float*  Cs  = reinterpret_cast<float*>(smc);
    float*  red = reinterpret_cast<float*>(smc + SM_RED_OFF);   // [64] sum | [64] sq
    int tid = threadIdx.x;
    int row0 = gb * 128;

#pragma unroll
    for (int i = tid; i < 2048; i += 256) {
        int row = i >> 4, c4 = (i & 15) * 4;
        float4 v = __ldcs(&reinterpret_cast<const float4*>(x + (ll)(row0 + row) * 64)[i & 15]);
        __half2 lo = __floats2half2_rn(v.x, v.y);
        __half2 hi = __floats2half2_rn(v.z, v.w);
        uint2 p;
        p.x = *reinterpret_cast<unsigned*>(&lo);
        p.y = *reinterpret_cast<unsigned*>(&hi);
        *reinterpret_cast<uint2*>(&xs[row * XS + c4]) = p;
    }
#pragma unroll
    for (int i = tid; i < 1024; i += 256) {
        int row = i >> 4, c4 = (i & 15) * 4;
        float4 v = reinterpret_cast<const float4*>(W)[i];
        __half2 lo = __floats2half2_rn(v.x, v.y);
        __half2 hi = __floats2half2_rn(v.z, v.w);
        uint2 p;
        p.x = *reinterpret_cast<unsigned*>(&lo);
        p.y = *reinterpret_cast<unsigned*>(&hi);
        *reinterpret_cast<uint2*>(&Wsf[row * WS + c4]) = p;
    }
    __syncthreads();

    int w = tid >> 5;
    wmma::fragment<wmma::accumulator, 16, 16, 16, float> acc[4];
#pragma unroll
    for (int n = 0; n < 4; n++) wmma::fill_fragment(acc[n], 0.0f);
#pragma unroll
    for (int k = 0; k < 4; k++) {
        wmma::fragment<wmma::matrix_a, 16, 16, 16, __half, wmma::row_major> af;
        wmma::load_matrix_sync(af, xs + (16 * w) * XS + 16 * k, XS);
#pragma unroll
        for (int n = 0; n < 4; n++) {
            wmma::fragment<wmma::matrix_b, 16, 16, 16, __half, wmma::row_major> bf;
            wmma::load_matrix_sync(bf, Wsf + (16 * k) * WS + 16 * n, WS);
            wmma::mma_sync(acc[n], af, bf, acc[n]);
        }
    }
    __syncthreads();   // all smem reads done; Cs overlaps xs/Wsf

#pragma unroll
    for (int n = 0; n < 4; n++)
        wmma::store_matrix_sync(Cs + (16 * w) * CSO + 16 * n, acc[n], CSO, wmma::mem_row_major);
    if (tid < 128) red[tid] = 0.f;
    __syncthreads();

    int cp = tid & 31;
    int rg = tid >> 5;
    float b0 = b[2 * cp], b1 = b[2 * cp + 1];
    float s0 = 0.f, q0 = 0.f, s1 = 0.f, q1 = 0.f;
    unsigned* hout = reinterpret_cast<unsigned*>(g_hh);
#pragma unroll
    for (int rr = 0; rr < 16; rr++) {
        int row = 16 * rg + rr;
        float2 v = *reinterpret_cast<float2*>(&Cs[row * CSO + 2 * cp]);
        float v0 = v.x + b0, v1 = v.y + b1;
        __half2 h2 = __floats2half2_rn(v0, v1);
        hout[(ll)(row0 + row) * 32 + cp] = *reinterpret_cast<unsigned*>(&h2);
        s0 += v0; q0 += v0 * v0; s1 += v1; q1 += v1 * v1;
    }
    atomicAdd(&red[2 * cp], s0);      atomicAdd(&red[2 * cp + 1], s1);
    atomicAdd(&red[64 + 2 * cp], q0); atomicAdd(&red[64 + 2 * cp + 1], q1);
    __syncthreads();
    if (tid < 64) {
        atomicAdd(&g_colsum[tid], red[tid]);
        atomicAdd(&g_colsq[tid],  red[64 + tid]);
    }
}

__device__ __forceinline__ void scatter_body(int sb, const int* __restrict__ ei) {
    int e = sb * 256 + threadIdx.x;
    int row = __ldcs(&ei[e]);
    int col = __ldcs(&ei[EE + e]);
    int p = atomicAdd(&g_cnt_i[col], 1);
    if (p < MAXDEG) g_adj[col * MAXDEG + p] = row;
}

__global__ __launch_bounds__(256) void fat_kernel(const float* __restrict__ x,
                                                  const float* __restrict__ W,
                                                  const float* __restrict__ b,
                                                  const int* __restrict__ ei) {
    extern __shared__ char smc[];
    int r = blockIdx.x % 9;
    int g = blockIdx.x / 9;
    if (r == 0) gemm_body(g, x, W, b, smc);
    else        scatter_body(g * 8 + (r - 1), ei);
}

// -------- fold BN into scale/shift; detect negative scales; reset stats --------
__global__ void scale_kernel(const float* __restrict__ gamma, const float* __restrict__ beta) {
    __shared__ int flag;
    int c = threadIdx.x;
    if (c == 0) flag = 0;
    __syncthreads();
    if (c < CC) {
        float mean = g_colsum[c] * (1.0f / NN);
        float var = g_colsq[c] * (1.0f / NN) - mean * mean;
        float sc = gamma[c] * rsqrtf(var + BN_EPS);
        g_scale[c] = sc;
        g_shift[c] = beta[c] - mean * sc;
        g_colsum[c] = 0.f;
        g_colsq[c] = 0.f;
        if (sc < 0.f) flag = 1;
    }
    __syncthreads();
    if (c == 0) g_negflag = flag;
}

// ======================= gather (R11 form, single full grid) -> out =======================
// 8 lanes per node; lane handles 8 channels (uint4). Neighbor indices from uniform
// int4 loads, prefetched one chunk ahead; bounds handled by selects.
// min-6-CTAs/SM: regs <= 42 -> 48 warps/SM (75% occ) for this latency-bound loop.
__global__ __launch_bounds__(256, 6) void gather_kernel(const float* __restrict__ pos) {
    int node = (blockIdx.x * blockDim.x + threadIdx.x) >> 3;
    int l = threadIdx.x & 7;
    int base8 = threadIdx.x & 24;
    unsigned int m8 = 0xFFu << base8;

    int cnt = min(g_cnt_i[node], MAXDEG);
    const int4* bucket4 = reinterpret_cast<const int4*>(&g_adj[(ll)node * MAXDEG]);
    float px = 0.f, py = 0.f, pz = 0.f;
    if (l == 0) {
        px = pos[node * 3 + 0];
        py = pos[node * 3 + 1];
        pz = pos[node * 3 + 2];
    }
    const uint4* h8 = reinterpret_cast<const uint4*>(g_hh);
    uint4 self = __ldg(&h8[(ll)node * 8 + l]);

    __half2 mx0 = *reinterpret_cast<__half2*>(&self.x);
    __half2 mx1 = *reinterpret_cast<__half2*>(&self.y);
    __half2 mx2 = *reinterpret_cast<__half2*>(&self.z);
    __half2 mx3 = *reinterpret_cast<__half2*>(&self.w);
    __half2 mn0 = mx0, mn1 = mx1, mn2 = mx2, mn3 = mx3;

    int vox = 0;
    if (l == 0) {
        int vx = min(max((int)floorf(px * GRID_INV), 0), NVOXD - 1);
        int vy = min(max((int)floorf(py * GRID_INV), 0), NVOXD - 1);
        int vz = min(max((int)floorf(pz * GRID_INV), 0), NVOXD - 1);
        vox = (vx * NVOXD + vy) * NVOXD + vz;
    }
    vox = __shfl_sync(m8, vox, base8);

    int neg = g_negflag;
    int nb4 = (cnt + 3) >> 2;
    int4 q = (nb4 > 0) ? __ldg(&bucket4[0]) : make_int4(node, node, node, node);

#define GATH_BODY(DOMIN)                                                        \
    for (int c = 0; c < nb4; c++) {                                             \
        int4 qn = (c + 1 < nb4) ? __ldg(&bucket4[c + 1]) : q;                   \
        int j0 = 4 * c;                                                         \
        int s0 = (j0 + 0 < cnt) ? q.x : node;                                   \
        int s1 = (j0 + 1 < cnt) ? q.y : node;                                   \
        int s2 = (j0 + 2 < cnt) ? q.z : node;                                   \
        int s3 = (j0 + 3 < cnt) ? q.w : node;                                   \
        uint4 u0 = __ldg(&h8[(ll)s0 * 8 + l]);                                  \
        uint4 u1 = __ldg(&h8[(ll)s1 * 8 + l]);                                  \
        uint4 u2 = __ldg(&h8[(ll)s2 * 8 + l]);                                  \
        uint4 u3 = __ldg(&h8[(ll)s3 * 8 + l]);                                  \
        const uint4* us[4] = {&u0, &u1, &u2, &u3};                              \
        _Pragma("unroll")                                                       \
        for (int t = 0; t < 4; t++) {                                           \
            __half2 a0 = *reinterpret_cast<const __half2*>(&us[t]->x);          \
            __half2 a1 = *reinterpret_cast<const __half2*>(&us[t]->y);          \
            __half2 a2 = *reinterpret_cast<const __half2*>(&us[t]->z);          \
            __half2 a3 = *reinterpret_cast<const __half2*>(&us[t]->w);          \
            mx0 = __hmax2(mx0, a0); mx1 = __hmax2(mx1, a1);                     \
            mx2 = __hmax2(mx2, a2); mx3 = __hmax2(mx3, a3);                     \
            if (DOMIN) {                                                        \
                mn0 = __hmin2(mn0, a0); mn1 = __hmin2(mn1, a1);                 \
                mn2 = __hmin2(mn2, a2); mn3 = __hmin2(mn3, a3);                 \
            }                                                                   \
        }                                                                       \
        q = qn;                                                                 \
    }

    if (!neg) { GATH_BODY(0) } else { GATH_BODY(1) }
#undef GATH_BODY

    float4 sca = *reinterpret_cast<const float4*>(&g_scale[8 * l]);
    float4 scb = *reinterpret_cast<const float4*>(&g_scale[8 * l + 4]);
    float4 sha = *reinterpret_cast<const float4*>(&g_shift[8 * l]);
    float4 shb = *reinterpret_cast<const float4*>(&g_shift[8 * l + 4]);

    float2 fx0 = __half22float2(mx0), fx1 = __half22float2(mx1);
    float2 fx2 = __half22float2(mx2), fx3 = __half22float2(mx3);

    float a0, a1, a2, a3, a4, a5, a6, a7;
    if (!neg) {
        a0 = fmaxf(fmaf(fx0.x, sca.x, sha.x), 0.f);
        a1 = fmaxf(fmaf(fx0.y, sca.y, sha.y), 0.f);
        a2 = fmaxf(fmaf(fx1.x, sca.z, sha.z), 0.f);
        a3 = fmaxf(fmaf(fx1.y, sca.w, sha.w), 0.f);
        a4 = fmaxf(fmaf(fx2.x, scb.x, shb.x), 0.f);
        a5 = fmaxf(fmaf(fx2.y, scb.y, shb.y), 0.f);
        a6 = fmaxf(fmaf(fx3.x, scb.z, shb.z), 0.f);
        a7 = fmaxf(fmaf(fx3.y, scb.w, shb.w), 0.f);
    } else {
        float2 fn0 = __half22float2(mn0), fn1 = __half22float2(mn1);
        float2 fn2 = __half22float2(mn2), fn3 = __half22float2(mn3);
        a0 = fmaxf(fmaxf(fmaf(fx0.x, sca.x, sha.x), fmaf(fn0.x, sca.x, sha.x)), 0.f);
        a1 = fmaxf(fmaxf(fmaf(fx0.y, sca.y, sha.y), fmaf(fn0.y, sca.y, sha.y)), 0.f);
        a2 = fmaxf(fmaxf(fmaf(fx1.x, sca.z, sha.z), fmaf(fn1.x, sca.z, sha.z)), 0.f);
        a3 = fmaxf(fmaxf(fmaf(fx1.y, sca.w, sha.w), fmaf(fn1.y, sca.w, sha.w)), 0.f);
        a4 = fmaxf(fmaxf(fmaf(fx2.x, scb.x, shb.x), fmaf(fn2.x, scb.x, shb.x)), 0.f);
        a5 = fmaxf(fmaxf(fmaf(fx2.y, scb.y, shb.y), fmaf(fn2.y, scb.y, shb.y)), 0.f);
        a6 = fmaxf(fmaxf(fmaf(fx3.x, scb.z, shb.z), fmaf(fn3.x, scb.z, shb.z)), 0.f);
        a7 = fmaxf(fmaxf(fmaf(fx3.y, scb.w, shb.w), fmaf(fn3.y, scb.w, shb.w)), 0.f);
    }

    float* xbase = &g_xsum[(ll)vox * 64 + 8 * l];
    asm volatile("red.global.add.v4.f32 [%0], {%1, %2, %3, %4};"
                 :: "l"(xbase), "f"(a0), "f"(a1), "f"(a2), "f"(a3) : "memory");
    asm volatile("red.global.add.v4.f32 [%0], {%1, %2, %3, %4};"
                 :: "l"(xbase + 4), "f"(a4), "f"(a5), "f"(a6), "f"(a7) : "memory");
    if (l == 0) {
        atomicAdd(&g_cnt[vox], 1.0f);
        atomicAdd(&g_psum[vox * 3 + 0], px);
        atomicAdd(&g_psum[vox * 3 + 1], py);
        atomicAdd(&g_psum[vox * 3 + 2], pz);
    }
}

// -------- finalize output [NVOX, 67] AND self-clean all accumulators for next replay ----
__global__ __launch_bounds__(256) void out_kernel(float* __restrict__ out) {
    int gid = blockIdx.x * blockDim.x + threadIdx.x;     // 262144 threads
    g_cnt_i[gid] = 0;

    int vox = gid >> 5;
    int lane = gid & 31;
    if (vox >= NVOX) return;

    float cntv = g_cnt[vox];
    float inv = 1.0f / fmaxf(cntv, 1.0f);

    float v0 = g_xsum[vox * 64 + lane];
    float v1 = g_xsum[vox * 64 + 32 + lane];
    float p = (lane < 3) ? g_psum[vox * 3 + lane] : 0.f;

    out[(ll)vox * 67 + lane] = v0 * inv;
    out[(ll)vox * 67 + 32 + lane] = v1 * inv;
    if (lane < 3) out[(ll)vox * 67 + 64 + lane] = p * inv;

    __syncwarp();
    g_xsum[vox * 64 + lane] = 0.f;
    g_xsum[vox * 64 + 32 + lane] = 0.f;
    if (lane < 3) g_psum[vox * 3 + lane] = 0.f;
    if (lane == 0) g_cnt[vox] = 0.f;
}

extern "C" void kernel_launch(void* const* d_in, const int* in_sizes, int n_in,
                              void* d_out, int out_size) {
    const float* x     = (const float*)d_in[0];  // [N, 64]
    const float* pos   = (const float*)d_in[1];  // [N, 3]
    const int*   ei    = (const int*)d_in[2];    // [2, E]
    const float* W     = (const float*)d_in[3];  // [64, 64]
    const float* b     = (const float*)d_in[4];  // [64]
    const float* gamma = (const float*)d_in[5];  // [64]
    const float* beta  = (const float*)d_in[6];  // [64]
    float* out = (float*)d_out;                  // [8000, 67]

    // Single stream, 4 launches (R14 configuration — measured best).
    fat_kernel<<<FAT_BLOCKS, 256, GS_SMEM_BYTES>>>(x, W, b, ei);       // 1
    scale_kernel<<<1, 64>>>(gamma, beta);                              // 2
    gather_kernel<<<NN * 8 / 256, 256>>>(pos);                         // 3
    out_kernel<<<NN / 256, 256>>>(out);                                // 4
}

// round 17
// speedup vs baseline: 1.1511x; 1.1511x over previous
#include <cuda_runtime.h>
#include <cuda_fp16.h>
#include <mma.h>
#include <stdint.h>

using namespace nvcuda;

// Problem constants
#define NN 262144
#define EE (NN * 16)
#define CC 64
#define NVOXD 20
#define NVOX 8000
#define BN_EPS 1e-5f
#define GRID_INV 2.0f   // 1/0.5
#define FULLMASK 0xFFFFFFFFu
#define MAXDEG 64

typedef unsigned long long ull;
typedef long long ll;

// -------- scratch (all load-time zero; out_kernel re-zeroes accumulators each replay) ----
__device__ __half g_hh[NN * CC];          // h = x@W+b in fp16
__device__ float g_colsum[CC];
__device__ float g_colsq[CC];
__device__ float g_scale[CC];
__device__ float g_shift[CC];
__device__ int   g_negflag;               // any(scale<0)?
__device__ float g_xsum[NVOX * CC];
__device__ float g_psum[NVOX * 3];
__device__ float g_cnt[NVOX];
__device__ int   g_cnt_i[NN];             // in-degree
__device__ int   g_adj[NN * MAXDEG + 4];  // fixed-capacity buckets

// ======================= FAT kernel: wmma GEMM+stats blocks + scatter blocks =======================
// 18432 blocks: blockIdx%9==0 -> GEMM block (2048), else scatter block (16384).
// Interleaving co-schedules both workloads on every SM: GEMM is tensor/smem/DRAM-read
// bound, scatter is L2-atomic bound -> near-disjoint resources.
#define XS 80
#define WS 80
#define CSO 72
#define SM_X_BYTES (128 * XS * 2)
#define SM_W_OFF   SM_X_BYTES
#define SM_C_BYTES (128 * CSO * 4)
#define SM_RED_OFF SM_C_BYTES
#define GS_SMEM_BYTES (SM_C_BYTES + 512)
#define GEMM_BLOCKS (NN / 128)            // 2048
#define SCAT_BLOCKS (EE / 256)            // 16384
#define FAT_BLOCKS (GEMM_BLOCKS + SCAT_BLOCKS)   // 18432 = 2048*9

__device__ __forceinline__ void gemm_body(int gb, const float* __restrict__ x,
                                          const float* __restrict__ W,
                                          const float* __restrict__ b,
                                          char* smc) {
    __half* xs  = reinterpret_cast<__half*>(smc);
    __half* Wsf = reinterpret_cast<__half*>(smc + SM_W_OFF);
    float*  Cs  = reinterpret_cast<float*>(smc);
    float*  red = reinterpret_cast<float*>(smc + SM_RED_OFF);   // [64] sum | [64] sq
    int tid = threadIdx.x;
    int row0 = gb * 128;

#pragma unroll
    for (int i = tid; i < 2048; i += 256) {
        int row = i >> 4, c4 = (i & 15) * 4;
        float4 v = __ldcs(&reinterpret_cast<const float4*>(x + (ll)(row0 + row) * 64)[i & 15]);
        __half2 lo = __floats2half2_rn(v.x, v.y);
        __half2 hi = __floats2half2_rn(v.z, v.w);
        uint2 p;
        p.x = *reinterpret_cast<unsigned*>(&lo);
        p.y = *reinterpret_cast<unsigned*>(&hi);
        *reinterpret_cast<uint2*>(&xs[row * XS + c4]) = p;
    }
#pragma unroll
    for (int i = tid; i < 1024; i += 256) {
        int row = i >> 4, c4 = (i & 15) * 4;
        float4 v = reinterpret_cast<const float4*>(W)[i];
        __half2 lo = __floats2half2_rn(v.x, v.y);
        __half2 hi = __floats2half2_rn(v.z, v.w);
        uint2 p;
        p.x = *reinterpret_cast<unsigned*>(&lo);
        p.y = *reinterpret_cast<unsigned*>(&hi);
        *reinterpret_cast<uint2*>(&Wsf[row * WS + c4]) = p;
    }
    __syncthreads();

    int w = tid >> 5;
    wmma::fragment<wmma::accumulator, 16, 16, 16, float> acc[4];
#pragma unroll
    for (int n = 0; n < 4; n++) wmma::fill_fragment(acc[n], 0.0f);
#pragma unroll
    for (int k = 0; k < 4; k++) {
        wmma::fragment<wmma::matrix_a, 16, 16, 16, __half, wmma::row_major> af;
        wmma::load_matrix_sync(af, xs + (16 * w) * XS + 16 * k, XS);
#pragma unroll
        for (int n = 0; n < 4; n++) {
            wmma::fragment<wmma::matrix_b, 16, 16, 16, __half, wmma::row_major> bf;
            wmma::load_matrix_sync(bf, Wsf + (16 * k) * WS + 16 * n, WS);
            wmma::mma_sync(acc[n], af, bf, acc[n]);
        }
    }
    __syncthreads();   // all smem reads done; Cs overlaps xs/Wsf

#pragma unroll
    for (int n = 0; n < 4; n++)
        wmma::store_matrix_sync(Cs + (16 * w) * CSO + 16 * n, acc[n], CSO, wmma::mem_row_major);
    if (tid < 128) red[tid] = 0.f;
    __syncthreads();

    int cp = tid & 31;
    int rg = tid >> 5;
    float b0 = b[2 * cp], b1 = b[2 * cp + 1];
    float s0 = 0.f, q0 = 0.f, s1 = 0.f, q1 = 0.f;
    unsigned* hout = reinterpret_cast<unsigned*>(g_hh);
#pragma unroll
    for (int rr = 0; rr < 16; rr++) {
        int row = 16 * rg + rr;
        float2 v = *reinterpret_cast<float2*>(&Cs[row * CSO + 2 * cp]);
        float v0 = v.x + b0, v1 = v.y + b1;
        __half2 h2 = __floats2half2_rn(v0, v1);
        hout[(ll)(row0 + row) * 32 + cp] = *reinterpret_cast<unsigned*>(&h2);
        s0 += v0; q0 += v0 * v0; s1 += v1; q1 += v1 * v1;
    }
    atomicAdd(&red[2 * cp], s0);      atomicAdd(&red[2 * cp + 1], s1);
    atomicAdd(&red[64 + 2 * cp], q0); atomicAdd(&red[64 + 2 * cp + 1], q1);
    __syncthreads();
    if (tid < 64) {
        atomicAdd(&g_colsum[tid], red[tid]);
        atomicAdd(&g_colsq[tid],  red[64 + tid]);
    }
}

__device__ __forceinline__ void scatter_body(int sb, const int* __restrict__ ei) {
    int e = sb * 256 + threadIdx.x;
    int row = __ldcs(&ei[e]);
    int col = __ldcs(&ei[EE + e]);
    int p = atomicAdd(&g_cnt_i[col], 1);
    if (p < MAXDEG) g_adj[col * MAXDEG + p] = row;
}

__global__ __launch_bounds__(256) void fat_kernel(const float* __restrict__ x,
                                                  const float* __restrict__ W,
                                                  const float* __restrict__ b,
                                                  const int* __restrict__ ei) {
    extern __shared__ char smc[];
    int r = blockIdx.x % 9;
    int g = blockIdx.x / 9;
    if (r == 0) gemm_body(g, x, W, b, smc);
    else        scatter_body(g * 8 + (r - 1), ei);
}

// -------- fold BN into scale/shift; detect negative scales; reset stats --------
__global__ void scale_kernel(const float* __restrict__ gamma, const float* __restrict__ beta) {
    __shared__ int flag;
    int c = threadIdx.x;
    if (c == 0) flag = 0;
    __syncthreads();
    if (c < CC) {
        float mean = g_colsum[c] * (1.0f / NN);
        float var = g_colsq[c] * (1.0f / NN) - mean * mean;
        float sc = gamma[c] * rsqrtf(var + BN_EPS);
        g_scale[c] = sc;
        g_shift[c] = beta[c] - mean * sc;
        g_colsum[c] = 0.f;
        g_colsq[c] = 0.f;
        if (sc < 0.f) flag = 1;
    }
    __syncthreads();
    if (c == 0) g_negflag = flag;
}

// ======================= gather (R11 form, single full grid) -> out =======================
// 8 lanes per node; lane handles 8 channels (uint4). Neighbor indices from uniform
// int4 loads, prefetched one chunk ahead; bounds handled by selects.
// (256,5): 48 regs, 5 CTAs/SM — measured optimum; (256,6) spills, ILP-2 regresses.
__global__ __launch_bounds__(256, 5) void gather_kernel(const float* __restrict__ pos) {
    int node = (blockIdx.x * blockDim.x + threadIdx.x) >> 3;
    int l = threadIdx.x & 7;
    int base8 = threadIdx.x & 24;
    unsigned int m8 = 0xFFu << base8;

    int cnt = min(g_cnt_i[node], MAXDEG);
    const int4* bucket4 = reinterpret_cast<const int4*>(&g_adj[(ll)node * MAXDEG]);
    float px = 0.f, py = 0.f, pz = 0.f;
    if (l == 0) {
        px = pos[node * 3 + 0];
        py = pos[node * 3 + 1];
        pz = pos[node * 3 + 2];
    }
    const uint4* h8 = reinterpret_cast<const uint4*>(g_hh);
    uint4 self = __ldg(&h8[(ll)node * 8 + l]);

    __half2 mx0 = *reinterpret_cast<__half2*>(&self.x);
    __half2 mx1 = *reinterpret_cast<__half2*>(&self.y);
    __half2 mx2 = *reinterpret_cast<__half2*>(&self.z);
    __half2 mx3 = *reinterpret_cast<__half2*>(&self.w);
    __half2 mn0 = mx0, mn1 = mx1, mn2 = mx2, mn3 = mx3;

    int vox = 0;
    if (l == 0) {
        int vx = min(max((int)floorf(px * GRID_INV), 0), NVOXD - 1);
        int vy = min(max((int)floorf(py * GRID_INV), 0), NVOXD - 1);
        int vz = min(max((int)floorf(pz * GRID_INV), 0), NVOXD - 1);
        vox = (vx * NVOXD + vy) * NVOXD + vz;
    }
    vox = __shfl_sync(m8, vox, base8);

    int neg = g_negflag;
    int nb4 = (cnt + 3) >> 2;
    int4 q = (nb4 > 0) ? __ldg(&bucket4[0]) : make_int4(node, node, node, node);

#define GATH_BODY(DOMIN)                                                        \
    for (int c = 0; c < nb4; c++) {                                             \
        int4 qn = (c + 1 < nb4) ? __ldg(&bucket4[c + 1]) : q;                   \
        int j0 = 4 * c;                                                         \
        int s0 = (j0 + 0 < cnt) ? q.x : node;                                   \
        int s1 = (j0 + 1 < cnt) ? q.y : node;                                   \
        int s2 = (j0 + 2 < cnt) ? q.z : node;                                   \
        int s3 = (j0 + 3 < cnt) ? q.w : node;                                   \
        uint4 u0 = __ldg(&h8[(ll)s0 * 8 + l]);                                  \
        uint4 u1 = __ldg(&h8[(ll)s1 * 8 + l]);                                  \
        uint4 u2 = __ldg(&h8[(ll)s2 * 8 + l]);                                  \
        uint4 u3 = __ldg(&h8[(ll)s3 * 8 + l]);                                  \
        const uint4* us[4] = {&u0, &u1, &u2, &u3};                              \
        _Pragma("unroll")                                                       \
        for (int t = 0; t < 4; t++) {                                           \
            __half2 a0 = *reinterpret_cast<const __half2*>(&us[t]->x);          \
            __half2 a1 = *reinterpret_cast<const __half2*>(&us[t]->y);          \
            __half2 a2 = *reinterpret_cast<const __half2*>(&us[t]->z);          \
            __half2 a3 = *reinterpret_cast<const __half2*>(&us[t]->w);          \
            mx0 = __hmax2(mx0, a0); mx1 = __hmax2(mx1, a1);                     \
            mx2 = __hmax2(mx2, a2); mx3 = __hmax2(mx3, a3);                     \
            if (DOMIN) {                                                        \
                mn0 = __hmin2(mn0, a0); mn1 = __hmin2(mn1, a1);                 \
                mn2 = __hmin2(mn2, a2); mn3 = __hmin2(mn3, a3);                 \
            }                                                                   \
        }                                                                       \
        q = qn;                                                                 \
    }

    if (!neg) { GATH_BODY(0) } else { GATH_BODY(1) }
#undef GATH_BODY

    float4 sca = *reinterpret_cast<const float4*>(&g_scale[8 * l]);
    float4 scb = *reinterpret_cast<const float4*>(&g_scale[8 * l + 4]);
    float4 sha = *reinterpret_cast<const float4*>(&g_shift[8 * l]);
    float4 shb = *reinterpret_cast<const float4*>(&g_shift[8 * l + 4]);

    float2 fx0 = __half22float2(mx0), fx1 = __half22float2(mx1);
    float2 fx2 = __half22float2(mx2), fx3 = __half22float2(mx3);

    float a0, a1, a2, a3, a4, a5, a6, a7;
    if (!neg) {
        a0 = fmaxf(fmaf(fx0.x, sca.x, sha.x), 0.f);
        a1 = fmaxf(fmaf(fx0.y, sca.y, sha.y), 0.f);
        a2 = fmaxf(fmaf(fx1.x, sca.z, sha.z), 0.f);
        a3 = fmaxf(fmaf(fx1.y, sca.w, sha.w), 0.f);
        a4 = fmaxf(fmaf(fx2.x, scb.x, shb.x), 0.f);
        a5 = fmaxf(fmaf(fx2.y, scb.y, shb.y), 0.f);
        a6 = fmaxf(fmaf(fx3.x, scb.z, shb.z), 0.f);
        a7 = fmaxf(fmaf(fx3.y, scb.w, shb.w), 0.f);
    } else {
        float2 fn0 = __half22float2(mn0), fn1 = __half22float2(mn1);
        float2 fn2 = __half22float2(mn2), fn3 = __half22float2(mn3);
        a0 = fmaxf(fmaxf(fmaf(fx0.x, sca.x, sha.x), fmaf(fn0.x, sca.x, sha.x)), 0.f);
        a1 = fmaxf(fmaxf(fmaf(fx0.y, sca.y, sha.y), fmaf(fn0.y, sca.y, sha.y)), 0.f);
        a2 = fmaxf(fmaxf(fmaf(fx1.x, sca.z, sha.z), fmaf(fn1.x, sca.z, sha.z)), 0.f);
        a3 = fmaxf(fmaxf(fmaf(fx1.y, sca.w, sha.w), fmaf(fn1.y, sca.w, sha.w)), 0.f);
        a4 = fmaxf(fmaxf(fmaf(fx2.x, scb.x, shb.x), fmaf(fn2.x, scb.x, shb.x)), 0.f);
        a5 = fmaxf(fmaxf(fmaf(fx2.y, scb.y, shb.y), fmaf(fn2.y, scb.y, shb.y)), 0.f);
        a6 = fmaxf(fmaxf(fmaf(fx3.x, scb.z, shb.z), fmaf(fn3.x, scb.z, shb.z)), 0.f);
        a7 = fmaxf(fmaxf(fmaf(fx3.y, scb.w, shb.w), fmaf(fn3.y, scb.w, shb.w)), 0.f);
    }

    float* xbase = &g_xsum[(ll)vox * 64 + 8 * l];
    asm volatile("red.global.add.v4.f32 [%0], {%1, %2, %3, %4};"
                 :: "l"(xbase), "f"(a0), "f"(a1), "f"(a2), "f"(a3) : "memory");
    asm volatile("red.global.add.v4.f32 [%0], {%1, %2, %3, %4};"
                 :: "l"(xbase + 4), "f"(a4), "f"(a5), "f"(a6), "f"(a7) : "memory");
    if (l == 0) {
        atomicAdd(&g_cnt[vox], 1.0f);
        atomicAdd(&g_psum[vox * 3 + 0], px);
        atomicAdd(&g_psum[vox * 3 + 1], py);
        atomicAdd(&g_psum[vox * 3 + 2], pz);
    }
}

// -------- finalize output [NVOX, 67] AND self-clean all accumulators for next replay ----
__global__ __launch_bounds__(256) void out_kernel(float* __restrict__ out) {
    int gid = blockIdx.x * blockDim.x + threadIdx.x;     // 262144 threads
    g_cnt_i[gid] = 0;

    int vox = gid >> 5;
    int lane = gid & 31;
    if (vox >= NVOX) return;

    float cntv = g_cnt[vox];
    float inv = 1.0f / fmaxf(cntv, 1.0f);

    float v0 = g_xsum[vox * 64 + lane];
    float v1 = g_xsum[vox * 64 + 32 + lane];
    float p = (lane < 3) ? g_psum[vox * 3 + lane] : 0.f;

    out[(ll)vox * 67 + lane] = v0 * inv;
    out[(ll)vox * 67 + 32 + lane] = v1 * inv;
    if (lane < 3) out[(ll)vox * 67 + 64 + lane] = p * inv;

    __syncwarp();
    g_xsum[vox * 64 + lane] = 0.f;
    g_xsum[vox * 64 + 32 + lane] = 0.f;
    if (lane < 3) g_psum[vox * 3 + lane] = 0.f;
    if (lane == 0) g_cnt[vox] = 0.f;
}

extern "C" void kernel_launch(void* const* d_in, const int* in_sizes, int n_in,
                              void* d_out, int out_size) {
    const float* x     = (const float*)d_in[0];  // [N, 64]
    const float* pos   = (const float*)d_in[1];  // [N, 3]
    const int*   ei    = (const int*)d_in[2];    // [2, E]
    const float* W     = (const float*)d_in[3];  // [64, 64]
    const float* b     = (const float*)d_in[4];  // [64]
    const float* gamma = (const float*)d_in[5];  // [64]
    const float* beta  = (const float*)d_in[6];  // [64]
    float* out = (float*)d_out;                  // [8000, 67]

    // Single stream, 4 launches (R14 configuration — measured best, 134.2 us).
    fat_kernel<<<FAT_BLOCKS, 256, GS_SMEM_BYTES>>>(x, W, b, ei);       // 1
    scale_kernel<<<1, 64>>>(gamma, beta);                              // 2
    gather_kernel<<<NN * 8 / 256, 256>>>(pos);                         // 3
    out_kernel<<<NN / 256, 256>>>(out);                                // 4
}